// round 9
// baseline (speedup 1.0000x reference)
#include <cuda_runtime.h>
#include <cuda_fp16.h>
#include <stdint.h>

#define NNODES_MAX 100000
#define NEDGES_MAX 3200000
#define F_IN 128
#define F4 32            // float4s per feature row
#define H2_ROW 32        // uint2 (4 halves) per feature row
#define SCAN_BLK 1024

// ---- scratch (static __device__ globals; allocation-free) ----
__device__ int    g_deg[NNODES_MAX];
__device__ int    g_off[NNODES_MAX];
__device__ int    g_bsum[128];
__device__ float  g_dinv[NNODES_MAX];
__device__ int    g_edge[NEDGES_MAX];                    // src per edge, dst-sorted
__device__ uint2  g_xh[(size_t)NNODES_MAX * H2_ROW];     // fp16(x * dinv[row])
__device__ __half g_wh[128 * 128];                       // combined [W_mu|W_ls] fp16, [k][j]
__device__ float  g_bias[128];                           // combined bias

// ---------------------------------------------------------------------------
// K0: zero degree counters
// ---------------------------------------------------------------------------
__global__ void k_zero(int n) {
    int v = blockIdx.x * blockDim.x + threadIdx.x;
    if (v < n) g_deg[v] = 0;
}

// ---------------------------------------------------------------------------
// K1: in-degree count
// ---------------------------------------------------------------------------
__global__ void k_count(const int* __restrict__ col, int E) {
    int i = blockIdx.x * blockDim.x + threadIdx.x;
    int base = i * 4;
    if (base + 3 < E) {
        int4 c = *reinterpret_cast<const int4*>(col + base);
        atomicAdd(&g_deg[c.x], 1);
        atomicAdd(&g_deg[c.y], 1);
        atomicAdd(&g_deg[c.z], 1);
        atomicAdd(&g_deg[c.w], 1);
    } else if (base < E) {
        for (int e = base; e < E; ++e) atomicAdd(&g_deg[col[e]], 1);
    }
}

// ---------------------------------------------------------------------------
// K2a: per-block exclusive scan of indeg -> g_off, block totals -> g_bsum
// ---------------------------------------------------------------------------
__global__ void k_scan_part(int n) {
    __shared__ int s[SCAN_BLK];
    int tid = threadIdx.x;
    int v = blockIdx.x * SCAN_BLK + tid;
    int val = (v < n) ? g_deg[v] : 0;
    s[tid] = val;
    __syncthreads();
    #pragma unroll
    for (int off = 1; off < SCAN_BLK; off <<= 1) {
        int t = (tid >= off) ? s[tid - off] : 0;
        __syncthreads();
        s[tid] += t;
        __syncthreads();
    }
    if (v < n) g_off[v] = s[tid] - val;
    if (tid == SCAN_BLK - 1) g_bsum[blockIdx.x] = s[tid];
}

// K2b: scan block sums
__global__ void k_scan_sums(int nb) {
    __shared__ int s[128];
    int tid = threadIdx.x;
    int val = (tid < nb) ? g_bsum[tid] : 0;
    s[tid] = val;
    __syncthreads();
    #pragma unroll
    for (int off = 1; off < 128; off <<= 1) {
        int t = (tid >= off) ? s[tid - off] : 0;
        __syncthreads();
        s[tid] += t;
        __syncthreads();
    }
    if (tid < nb) g_bsum[tid] = s[tid] - val;
}

// ---------------------------------------------------------------------------
// K3: fused scan_add + prescale. One warp per node.
//   g_off[v] += block base; dinv = rsqrt(deg+1); g_deg -> 0 (cursor);
//   g_xh[v][:] = fp16(x[v][:] * dinv)
// n*32 threads; each lane converts 4 features.
// ---------------------------------------------------------------------------
__global__ void k_prep(const float* __restrict__ x, int n) {
    int idx = blockIdx.x * blockDim.x + threadIdx.x;
    if (idx >= n * F4) return;
    int v    = idx >> 5;
    int lane = idx & 31;

    int deg = g_deg[v];
    __syncwarp();                      // deg read before cursor reset
    if (lane == 0) {
        g_off[v] += g_bsum[v >> 10];   // v / SCAN_BLK
        g_deg[v] = 0;                  // placement cursor
    }
    float dv = rsqrtf((float)(deg + 1));
    if (lane == 0) g_dinv[v] = dv;

    float4 xv = reinterpret_cast<const float4*>(x)[idx];
    __half2 h0 = __floats2half2_rn(xv.x * dv, xv.y * dv);
    __half2 h1 = __floats2half2_rn(xv.z * dv, xv.w * dv);
    uint2 o;
    o.x = *reinterpret_cast<unsigned*>(&h0);
    o.y = *reinterpret_cast<unsigned*>(&h1);
    g_xh[idx] = o;
}

// ---------------------------------------------------------------------------
// K4: permute edges into dst-sorted order (src index only, 4B records)
// ---------------------------------------------------------------------------
__global__ void k_permute(const int* __restrict__ rowi,
                          const int* __restrict__ coli, int E) {
    int i = blockIdx.x * blockDim.x + threadIdx.x;
    int base = i * 4;
    if (base + 3 < E) {
        int4 s4 = *reinterpret_cast<const int4*>(rowi + base);
        int4 d4 = *reinterpret_cast<const int4*>(coli + base);
        g_edge[g_off[d4.x] + atomicAdd(&g_deg[d4.x], 1)] = s4.x;
        g_edge[g_off[d4.y] + atomicAdd(&g_deg[d4.y], 1)] = s4.y;
        g_edge[g_off[d4.z] + atomicAdd(&g_deg[d4.z], 1)] = s4.z;
        g_edge[g_off[d4.w] + atomicAdd(&g_deg[d4.w], 1)] = s4.w;
    } else if (base < E) {
        for (int e = base; e < E; ++e) {
            int s = rowi[e], d = coli[e];
            g_edge[g_off[d] + atomicAdd(&g_deg[d], 1)] = s;
        }
    }
}

// ---------------------------------------------------------------------------
// K5: convert W -> fp16 combined layout [k][j] (j<64: mu, else logstd); bias
// ---------------------------------------------------------------------------
__global__ void k_wconv(const float* __restrict__ Wmu, const float* __restrict__ bmu,
                        const float* __restrict__ Wls, const float* __restrict__ bls) {
    int i = blockIdx.x * blockDim.x + threadIdx.x;
    if (i < 128 * 128) {
        int k = i >> 7, j = i & 127;
        float w = (j < 64) ? Wmu[k * 64 + j] : Wls[k * 64 + (j - 64)];
        g_wh[i] = __float2half_rn(w);
    }
    if (i < 128) g_bias[i] = (i < 64) ? bmu[i] : bls[i - 64];
}

// ---------------------------------------------------------------------------
// K6: FUSED gather + HMMA GEMM.
// Block: 256 threads (8 warps), 128-row tile.
// Phase 1: warp w gathers nodes [rowbase+16w, rowbase+16w+16) into smem A
//          (fp32 accumulate over fp16 rows, fp16 result into A tile).
// Phase 2: HMMA m16n8k16 over A[128][136] x W[128][136], bias epilogue,
//          mu/logstd split at col 64.
// ---------------------------------------------------------------------------
__global__ void k_gather_gemm(float* __restrict__ out, int n) {
    extern __shared__ __half sm[];
    __half* As = sm;                         // 128*136
    __half* Ws = sm + 128 * 136;             // 128*136
    float*  bs = (float*)(sm + 2 * 128 * 136);

    int tid  = threadIdx.x;
    int warp = tid >> 5, lane = tid & 31;
    int rowbase = blockIdx.x * 128;

    // load W tile + bias
    {
        const uint4* src = reinterpret_cast<const uint4*>(g_wh);
        for (int t = tid; t < 128 * 16; t += 256) {
            int r = t >> 4, c = t & 15;
            *reinterpret_cast<uint4*>(Ws + r * 136 + c * 8) = src[r * 16 + c];
        }
    }
    if (tid < 128) bs[tid] = g_bias[tid];

    // Phase 1: gather 16 nodes per warp into As
    for (int r = warp * 16; r < warp * 16 + 16; ++r) {
        int v = rowbase + r;
        if (v >= n) {
            *reinterpret_cast<uint2*>(&As[r * 136 + lane * 4]) = make_uint2(0, 0);
            continue;
        }
        float dv_dst = g_dinv[v];
        int offs = g_off[v];
        int cnt  = g_deg[v];

        float ax, ay, az, aw;
        {
            uint2 h = __ldg(&g_xh[(size_t)v * H2_ROW + lane]);
            float2 f0 = __half22float2(*reinterpret_cast<__half2*>(&h.x));
            float2 f1 = __half22float2(*reinterpret_cast<__half2*>(&h.y));
            ax = f0.x; ay = f0.y; az = f1.x; aw = f1.y;
        }

        for (int base = 0; base < cnt; base += 32) {
            int m = min(32, cnt - base);
            int s = 0;
            if (base + lane < cnt) s = __ldg(&g_edge[offs + base + lane]);

            int e = 0;
            for (; e + 3 < m; e += 4) {
                int s0 = __shfl_sync(0xffffffffu, s, e);
                int s1 = __shfl_sync(0xffffffffu, s, e + 1);
                int s2 = __shfl_sync(0xffffffffu, s, e + 2);
                int s3 = __shfl_sync(0xffffffffu, s, e + 3);
                uint2 h0 = __ldg(&g_xh[(size_t)s0 * H2_ROW + lane]);
                uint2 h1 = __ldg(&g_xh[(size_t)s1 * H2_ROW + lane]);
                uint2 h2 = __ldg(&g_xh[(size_t)s2 * H2_ROW + lane]);
                uint2 h3 = __ldg(&g_xh[(size_t)s3 * H2_ROW + lane]);
                float2 a, b;
                a = __half22float2(*reinterpret_cast<__half2*>(&h0.x));
                b = __half22float2(*reinterpret_cast<__half2*>(&h0.y));
                ax += a.x; ay += a.y; az += b.x; aw += b.y;
                a = __half22float2(*reinterpret_cast<__half2*>(&h1.x));
                b = __half22float2(*reinterpret_cast<__half2*>(&h1.y));
                ax += a.x; ay += a.y; az += b.x; aw += b.y;
                a = __half22float2(*reinterpret_cast<__half2*>(&h2.x));
                b = __half22float2(*reinterpret_cast<__half2*>(&h2.y));
                ax += a.x; ay += a.y; az += b.x; aw += b.y;
                a = __half22float2(*reinterpret_cast<__half2*>(&h3.x));
                b = __half22float2(*reinterpret_cast<__half2*>(&h3.y));
                ax += a.x; ay += a.y; az += b.x; aw += b.y;
            }
            for (; e < m; ++e) {
                int s0 = __shfl_sync(0xffffffffu, s, e);
                uint2 h0 = __ldg(&g_xh[(size_t)s0 * H2_ROW + lane]);
                float2 a = __half22float2(*reinterpret_cast<__half2*>(&h0.x));
                float2 b = __half22float2(*reinterpret_cast<__half2*>(&h0.y));
                ax += a.x; ay += a.y; az += b.x; aw += b.y;
            }
        }

        __half2 h0 = __floats2half2_rn(ax * dv_dst, ay * dv_dst);
        __half2 h1 = __floats2half2_rn(az * dv_dst, aw * dv_dst);
        uint2 o;
        o.x = *reinterpret_cast<unsigned*>(&h0);
        o.y = *reinterpret_cast<unsigned*>(&h1);
        *reinterpret_cast<uint2*>(&As[r * 136 + lane * 4]) = o;
    }
    __syncthreads();

    // Phase 2: HMMA
    int m0 = warp * 16;
    float c[16][4];
    #pragma unroll
    for (int t = 0; t < 16; ++t) { c[t][0] = c[t][1] = c[t][2] = c[t][3] = 0.f; }

    uint32_t a_base = (uint32_t)__cvta_generic_to_shared(As);
    uint32_t b_base = (uint32_t)__cvta_generic_to_shared(Ws);

    #pragma unroll
    for (int kk = 0; kk < 8; ++kk) {
        int k0 = kk * 16;
        uint32_t a0, a1, a2, a3;
        {
            int r   = m0 + (lane & 15);
            int col = k0 + 8 * (lane >> 4);
            uint32_t addr = a_base + (uint32_t)(r * 136 + col) * 2u;
            asm volatile(
                "ldmatrix.sync.aligned.m8n8.x4.shared.b16 {%0,%1,%2,%3}, [%4];"
                : "=r"(a0), "=r"(a1), "=r"(a2), "=r"(a3) : "r"(addr));
        }
        #pragma unroll
        for (int nt = 0; nt < 16; ++nt) {
            uint32_t b0, b1;
            int r = k0 + (lane & 15);
            uint32_t addr = b_base + (uint32_t)(r * 136 + nt * 8) * 2u;
            asm volatile(
                "ldmatrix.sync.aligned.m8n8.x2.trans.shared.b16 {%0,%1}, [%2];"
                : "=r"(b0), "=r"(b1) : "r"(addr));
            asm volatile(
                "mma.sync.aligned.m16n8k16.row.col.f32.f16.f16.f32 "
                "{%0,%1,%2,%3}, {%4,%5,%6,%7}, {%8,%9}, {%0,%1,%2,%3};"
                : "+f"(c[nt][0]), "+f"(c[nt][1]), "+f"(c[nt][2]), "+f"(c[nt][3])
                : "r"(a0), "r"(a1), "r"(a2), "r"(a3), "r"(b0), "r"(b1));
        }
    }

    // epilogue: bias + split mu/logstd
    int g  = lane >> 2;
    int t4 = lane & 3;
    float* outm = out;
    float* outl = out + (size_t)n * 64;
    #pragma unroll
    for (int nt = 0; nt < 16; ++nt) {
        int col = nt * 8 + t4 * 2;
        float bi0 = bs[col], bi1 = bs[col + 1];
        int v0 = rowbase + m0 + g;
        int v1 = v0 + 8;
        if (col < 64) {
            if (v0 < n)
                *reinterpret_cast<float2*>(outm + (size_t)v0 * 64 + col) =
                    make_float2(c[nt][0] + bi0, c[nt][1] + bi1);
            if (v1 < n)
                *reinterpret_cast<float2*>(outm + (size_t)v1 * 64 + col) =
                    make_float2(c[nt][2] + bi0, c[nt][3] + bi1);
        } else {
            int cl = col - 64;
            if (v0 < n)
                *reinterpret_cast<float2*>(outl + (size_t)v0 * 64 + cl) =
                    make_float2(c[nt][0] + bi0, c[nt][1] + bi1);
            if (v1 < n)
                *reinterpret_cast<float2*>(outl + (size_t)v1 * 64 + cl) =
                    make_float2(c[nt][2] + bi0, c[nt][3] + bi1);
        }
    }
}

// ---------------------------------------------------------------------------
// launch
// ---------------------------------------------------------------------------
extern "C" void kernel_launch(void* const* d_in, const int* in_sizes, int n_in,
                              void* d_out, int out_size) {
    const float* x   = (const float*)d_in[0];
    const int*   ei  = (const int*)d_in[1];
    const float* Wmu = (const float*)d_in[2];
    const float* bmu = (const float*)d_in[3];
    const float* Wls = (const float*)d_in[4];
    const float* bls = (const float*)d_in[5];

    int n = in_sizes[0] / F_IN;     // 100000
    int E = in_sizes[1] / 2;        // 3200000
    const int* rowi = ei;           // edge_index[0] (src)
    const int* coli = ei + E;       // edge_index[1] (dst)

    int nb = (n + SCAN_BLK - 1) / SCAN_BLK;   // 98

    k_zero<<<(n + 255) / 256, 256>>>(n);
    k_count<<<((E + 3) / 4 + 255) / 256, 256>>>(coli, E);
    k_scan_part<<<nb, SCAN_BLK>>>(n);
    k_scan_sums<<<1, 128>>>(nb);
    k_prep<<<(n * F4 + 255) / 256, 256>>>(x, n);
    k_permute<<<((E + 3) / 4 + 255) / 256, 256>>>(rowi, coli, E);
    k_wconv<<<64, 256>>>(Wmu, bmu, Wls, bls);

    int smem_bytes = 2 * 128 * 136 * (int)sizeof(__half) + 128 * (int)sizeof(float);
    cudaFuncSetAttribute(k_gather_gemm, cudaFuncAttributeMaxDynamicSharedMemorySize,
                         smem_bytes);
    k_gather_gemm<<<(n + 127) / 128, 256, smem_bytes>>>((float*)d_out, n);
}